// round 16
// baseline (speedup 1.0000x reference)
#include <cuda_runtime.h>
#include <cuda_fp16.h>
#include <cstdint>
#include <math.h>

#define S_LEN   2048
#define D_MODEL 2048
#define HID     5632
#define NH      32
#define NKV     8
#define HD      64
#define QKV_N   3072        // 2048 q | 512 k | 512 v
#define W13_N   11264       // 5632 g1 | 5632 g3 (interleaved 64/64 per 128-tile)
#define TILE_B  16384

// ---------------- fp32 scratch ------------------------------------------------
__device__ __align__(1024) float g_qkv[S_LEN * QKV_N];   // only V cols written/read
__device__ __align__(1024) float g_x1 [S_LEN * D_MODEL];

// ---------------- fp16 scratch ------------------------------------------------
__device__ __align__(1024) __half t_h_hi  [S_LEN * D_MODEL];
__device__ __align__(1024) __half t_ctx_hi[S_LEN * D_MODEL];
__device__ __align__(1024) __half t_g_hi  [S_LEN * HID];
__device__ __align__(1024) __half t_wqkv_hi[QKV_N * D_MODEL];
__device__ __align__(1024) __half t_wo_hi [D_MODEL * D_MODEL];
__device__ __align__(1024) __half t_w13_hi[W13_N * D_MODEL];
__device__ __align__(1024) __half t_w2_hi [D_MODEL * HID];
__device__ __align__(1024) __half t_qat_hi[NH  * 16 * 8192];
__device__ __align__(1024) __half t_kat_hi[NKV * 16 * 8192];
__device__ __align__(1024) __half t_vat_hi[NKV * 16 * 8192];

// ---------------- PTX helpers (baseline PTX only) -----------------------------
__device__ __forceinline__ uint32_t smem_u32(const void* p) {
    uint32_t a;
    asm("{ .reg .u64 t; cvta.to.shared.u64 t, %1; cvt.u32.u64 %0, t; }" : "=r"(a) : "l"(p));
    return a;
}
#define MBAR_INIT(a, c) asm volatile("mbarrier.init.shared.b64 [%0], %1;" :: "r"(a), "r"(c) : "memory")
#define MBAR_EXPECT(a, b) asm volatile("mbarrier.arrive.expect_tx.shared.b64 _, [%0], %1;" :: "r"(a), "r"(b) : "memory")
__device__ __forceinline__ void mbar_wait(uint32_t mbar, uint32_t parity) {
    asm volatile(
        "{\n\t.reg .pred P1;\n\t"
        "W_%=:\n\t"
        "mbarrier.try_wait.parity.acquire.cta.shared::cta.b64 P1, [%0], %1, 0x989680;\n\t"
        "@P1 bra.uni D_%=;\n\t"
        "bra.uni W_%=;\n\t"
        "D_%=:\n\t}"
        :: "r"(mbar), "r"(parity) : "memory");
}
__device__ __forceinline__ void bulk_g2s(uint32_t dst, const void* src, uint32_t bytes, uint32_t mbar) {
    asm volatile("cp.async.bulk.shared::cta.global.mbarrier::complete_tx::bytes [%0], [%1], %2, [%3];"
        :: "r"(dst), "l"(src), "r"(bytes), "r"(mbar) : "memory");
}
#define LDSM4(r, a) \
    asm volatile("ldmatrix.sync.aligned.m8n8.x4.shared.b16 {%0,%1,%2,%3}, [%4];" \
        : "=r"((r)[0]), "=r"((r)[1]), "=r"((r)[2]), "=r"((r)[3]) : "r"(a))
#define MMA_F16(d, a, b) \
    asm volatile("mma.sync.aligned.m16n8k16.row.col.f32.f16.f16.f32 " \
        "{%0,%1,%2,%3}, {%4,%5,%6,%7}, {%8,%9}, {%0,%1,%2,%3};" \
        : "+f"((d)[0]), "+f"((d)[1]), "+f"((d)[2]), "+f"((d)[3]) \
        : "r"((a)[0]), "r"((a)[1]), "r"((a)[2]), "r"((a)[3]), "r"((b)[0]), "r"((b)[1]))

__device__ __forceinline__ uint32_t pack_h2(float a, float b) {
    __half2 t = __floats2half2_rn(a, b);
    return *(uint32_t*)&t;
}

// ---------------- mma.sync GEMM (2-stage pipeline, 2 CTAs/SM) ----------------
// mode 0: C fp32 (+R)
// mode 1: qkv — rope Q (-> PQ), K (-> PK); V cols >= 2560 -> C fp32
// mode 3: fused W13 -> silu(g1)*g3 -> gb A-tiles (PQ)
// smem layout: stages [0, 64K); mode-3 sf buffer overlaps [0, 67584); mbars at 69568.
#define GEMM_MB_OFF 69568u
#define GEMM_SMEM   69632
__global__ void __launch_bounds__(256, 2) mma_gemm(
    const __half* __restrict__ Ahi, const __half* __restrict__ Bhi,
    const float* __restrict__ R, float* __restrict__ C, int M, int N, int K, int mode,
    __half* __restrict__ PQ, __half* __restrict__ PK)
{
    extern __shared__ char smem[];
    uint32_t sb = smem_u32(smem);
    int tid = threadIdx.x, wid = tid >> 5, ln = tid & 31;
    int wm = wid >> 2, wn = wid & 3;
    int mt = blockIdx.y, nt = blockIdx.x;
    int MT = M >> 7, NT = N >> 7, KTt = K >> 6;
    uint32_t mb0 = sb + GEMM_MB_OFF;

    if (tid == 0) { MBAR_INIT(mb0, 1); MBAR_INIT(mb0 + 8, 1); }
    __syncthreads();

    auto issue = [&](int s, int kt) {
        uint32_t mb = mb0 + s * 8;
        uint32_t dst = sb + s * (2 * TILE_B);
        size_t aoff = ((size_t)kt * MT + mt) * (size_t)(128 * 64);
        size_t boff = ((size_t)kt * NT + nt) * (size_t)(128 * 64);
        MBAR_EXPECT(mb, 2 * TILE_B);
        bulk_g2s(dst,          Ahi + aoff, TILE_B, mb);
        bulk_g2s(dst + TILE_B, Bhi + boff, TILE_B, mb);
    };
    if (tid == 0) {
        issue(0, 0);
        if (KTt > 1) issue(1, 1);
    }

    float acc[4][4][4];
#pragma unroll
    for (int i = 0; i < 4; i++)
#pragma unroll
        for (int j = 0; j < 4; j++)
#pragma unroll
            for (int r = 0; r < 4; r++) acc[i][j][r] = 0.f;

    int arow0 = wm * 64 + (ln & 7) + ((ln & 8) ? 8 : 0);
    int acgs  = (ln >> 4) & 1;
    int brow0 = wn * 32 + (ln & 7) + ((ln & 16) ? 8 : 0);
    int bcgs  = (ln >> 3) & 1;

    for (int kt = 0; kt < KTt; kt++) {
        int s = kt & 1, ph = (kt >> 1) & 1;
        mbar_wait(mb0 + s * 8, ph);
        uint32_t st = sb + s * (2 * TILE_B);
        uint32_t Ah = st, Bh = st + TILE_B;
#pragma unroll
        for (int ks = 0; ks < 4; ks++) {
            int acg = ks * 2 + acgs;
            int bcg = ks * 2 + bcgs;
            uint32_t ahr[16], bhr[8];
#pragma unroll
            for (int fm = 0; fm < 4; fm++) {
                int row = arow0 + fm * 16;
                uint32_t off = (uint32_t)(row * 128) + (uint32_t)((acg ^ (row & 7)) << 4);
                LDSM4(ahr + fm * 4, Ah + off);
            }
#pragma unroll
            for (int pr = 0; pr < 2; pr++) {
                int row = brow0 + pr * 16;
                uint32_t off = (uint32_t)(row * 128) + (uint32_t)((bcg ^ (row & 7)) << 4);
                LDSM4(bhr + pr * 4, Bh + off);
            }
#pragma unroll
            for (int fm = 0; fm < 4; fm++)
#pragma unroll
                for (int fn = 0; fn < 4; fn++)
                    MMA_F16(acc[fm][fn], ahr + fm * 4, bhr + fn * 2);
        }
        __syncthreads();
        if (tid == 0 && kt + 2 < KTt) issue(s, kt + 2);
    }

    int qr = ln >> 2, qc = ln & 3;

    if (mode == 3) {
        // stage fp32 accs to smem [128][132] (overlaps stage area; mainloop done)
        float* sf = (float*)smem;
        __syncthreads();
#pragma unroll
        for (int fm = 0; fm < 4; fm++) {
            int rl = wm * 64 + fm * 16 + qr;
#pragma unroll
            for (int fn = 0; fn < 4; fn++) {
                int col = wn * 32 + fn * 8 + 2 * qc;
                sf[rl * 132 + col]           = acc[fm][fn][0];
                sf[rl * 132 + col + 1]       = acc[fm][fn][1];
                sf[(rl + 8) * 132 + col]     = acc[fm][fn][2];
                sf[(rl + 8) * 132 + col + 1] = acc[fm][fn][3];
            }
        }
        __syncthreads();
        size_t tile = ((size_t)nt * MT + mt) * (size_t)TILE_B;
#pragma unroll
        for (int i = 0; i < 4; i++) {
            int ch = tid + 256 * i;         // 0..1023
            int r = ch >> 3, c8 = ch & 7;
            __half h8[8];
#pragma unroll
            for (int u = 0; u < 8; u++) {
                float a = sf[r * 132 + c8 * 8 + u];
                float c = sf[r * 132 + 64 + c8 * 8 + u];
                float sig = 1.0f / (1.0f + expf(-a));
                h8[u] = __float2half_rn(a * sig * c);
            }
            uint32_t off = (uint32_t)(r * 128) + (uint32_t)((c8 ^ (r & 7)) << 4);
            *(uint4*)((char*)PQ + tile + off) = *(uint4*)h8;
        }
        return;
    }

    float freqs[4];
    if (mode == 1) {
#pragma unroll
        for (int fn = 0; fn < 4; fn++) {
            int col = nt * 128 + wn * 32 + fn * 8 + 2 * qc;
            int i = (col & 63) >> 1;
            freqs[fn] = 1.0f / powf(10000.0f, (2.0f * (float)i) / 64.0f);
        }
    }

#pragma unroll
    for (int fm = 0; fm < 4; fm++) {
        int row0 = mt * 128 + wm * 64 + fm * 16 + qr;
#pragma unroll
        for (int fn = 0; fn < 4; fn++) {
            int col = nt * 128 + wn * 32 + fn * 8 + 2 * qc;
            if (mode == 0) {
                size_t i0 = (size_t)row0 * N + col;
                size_t i1 = (size_t)(row0 + 8) * N + col;
                float2 v0 = make_float2(acc[fm][fn][0], acc[fm][fn][1]);
                float2 v1 = make_float2(acc[fm][fn][2], acc[fm][fn][3]);
                if (R) {
                    float2 r0 = *(const float2*)&R[i0];
                    float2 r1 = *(const float2*)&R[i1];
                    v0.x += r0.x; v0.y += r0.y; v1.x += r1.x; v1.y += r1.y;
                }
                *(float2*)&C[i0] = v0;
                *(float2*)&C[i1] = v1;
            } else {   // mode 1: qkv
                if (col >= 2560) {
                    size_t i0 = (size_t)row0 * N + col;
                    size_t i1 = (size_t)(row0 + 8) * N + col;
                    *(float2*)&C[i0] = make_float2(acc[fm][fn][0], acc[fm][fn][1]);
                    *(float2*)&C[i1] = make_float2(acc[fm][fn][2], acc[fm][fn][3]);
                } else {
                    float freq = freqs[fn];
                    int isq = (col < 2048);
                    int head = isq ? (col >> 6) : ((col - 2048) >> 6);
                    __half* Hp = isq ? PQ : PK;
                    int c8 = (col & 63) >> 3;
                    uint32_t inoff = (uint32_t)((col & 7) * 2);
#pragma unroll
                    for (int rr = 0; rr < 2; rr++) {
                        int row = row0 + rr * 8;
                        float v0 = acc[fm][fn][rr * 2], v1 = acc[fm][fn][rr * 2 + 1];
                        float sn, cs; sincosf((float)row * freq, &sn, &cs);
                        float orr = v0 * cs - v1 * sn;
                        float oii = v0 * sn + v1 * cs;
                        int r = row & 127;
                        size_t tile = ((size_t)head * 16 + (row >> 7)) * (size_t)TILE_B;
                        uint32_t off = (uint32_t)(r * 128) + (uint32_t)((c8 ^ (r & 7)) << 4) + inoff;
                        *(uint32_t*)((char*)Hp + tile + off) = pack_h2(orr, oii);
                    }
                }
            }
        }
    }
}

// ---------------- tensorized flash attention (single-pass fp16) --------------
#define ATT_SQ    0u
#define ATT_SMSK  16384u
#define ATT_SST   24576u
#define ATT_MB    (24576u + 131072u)
#define ATT_SMEM  (24576 + 131072 + 64)
__global__ void __launch_bounds__(256, 1) attn_mma(
    const __half* __restrict__ Qhi,
    const __half* __restrict__ Khi, const __half* __restrict__ Vhi,
    const int* __restrict__ mask,
    __half* __restrict__ Chi)
{
    extern __shared__ char smem[];
    uint32_t sb = smem_u32(smem);
    int tid = threadIdx.x, wid = tid >> 5, ln = tid & 31;
    int qb = blockIdx.x, h = blockIdx.y;
    int kvh = h >> 2;
    int q2 = (ln & 3) * 2;

    int* msk = (int*)(smem + ATT_SMSK);
    for (int i = tid; i < S_LEN; i += 256) msk[i] = mask[i];
    {
        const uint4* qs0 = (const uint4*)(Qhi + ((size_t)h * 16 + qb) * 8192);
        uint4* qd0 = (uint4*)(smem + ATT_SQ);
        for (int i = tid; i < 1024; i += 256) qd0[i] = qs0[i];
    }
    uint32_t mb0 = sb + ATT_MB;
    if (tid == 0) {
        MBAR_INIT(mb0, 1); MBAR_INIT(mb0 + 8, 1);
        MBAR_INIT(mb0 + 16, 1); MBAR_INIT(mb0 + 24, 1);
    }
    __syncthreads();

    auto issue = [&](int s, int kb) {
        uint32_t mb = mb0 + s * 8;
        uint32_t dst = sb + ATT_SST + s * 32768;
        size_t ko = ((size_t)kvh * 16 + kb) * 8192;
        MBAR_EXPECT(mb, 32768);
        bulk_g2s(dst,         Khi + ko, 16384, mb);
        bulk_g2s(dst + 16384, Vhi + ko, 16384, mb);
    };
    if (tid == 0) { issue(0, 0); issue(1, 1); issue(2, 2); issue(3, 3); }

    uint32_t qh[4][4];
    {
        int arow0 = wid * 16 + (ln & 7) + ((ln & 8) ? 8 : 0);
        int acgs = (ln >> 4) & 1;
#pragma unroll
        for (int ks = 0; ks < 4; ks++) {
            int cg = ks * 2 + acgs;
            uint32_t off = (uint32_t)(arow0 * 128) + (uint32_t)((cg ^ (arow0 & 7)) << 4);
            LDSM4(qh[ks], sb + ATT_SQ + off);
        }
    }

    float mrow0 = -INFINITY, mrow1 = -INFINITY, lrow0 = 0.f, lrow1 = 0.f;
    float cacc[8][4];
#pragma unroll
    for (int j = 0; j < 8; j++)
#pragma unroll
        for (int r = 0; r < 4; r++) cacc[j][r] = 0.f;

    int brow_b = (ln & 7) + ((ln & 16) ? 8 : 0);
    int bcgs = (ln >> 3) & 1;

    for (int kb = 0; kb < 16; kb++) {
        int s = kb & 3, ph = (kb >> 2) & 1;
        mbar_wait(mb0 + s * 8, ph);
        uint32_t st = sb + ATT_SST + s * 32768;
        uint32_t Kh = st, Vh = st + 16384;

        float sacc[16][4];
#pragma unroll
        for (int j = 0; j < 16; j++)
#pragma unroll
            for (int r = 0; r < 4; r++) sacc[j][r] = 0.f;
#pragma unroll
        for (int nj = 0; nj < 4; nj++) {
#pragma unroll
            for (int ks = 0; ks < 4; ks++) {
                uint32_t bh[8];
                int cg = ks * 2 + bcgs;
#pragma unroll
                for (int pr = 0; pr < 2; pr++) {
                    int row = nj * 32 + pr * 16 + brow_b;
                    uint32_t off = (uint32_t)(row * 128) + (uint32_t)((cg ^ (row & 7)) << 4);
                    LDSM4(bh + pr * 4, Kh + off);
                }
#pragma unroll
                for (int nt = 0; nt < 4; nt++) {
                    float* d = sacc[nj * 4 + nt];
                    uint32_t* rh = bh + (nt >> 1) * 4 + (nt & 1) * 2;
                    MMA_F16(d, qh[ks], rh);
                }
            }
        }
        float tmax0 = -INFINITY, tmax1 = -INFINITY;
#pragma unroll
        for (int j = 0; j < 16; j++) {
            int c = kb * 128 + 8 * j + q2;
            sacc[j][0] = msk[c]     ? sacc[j][0] * 0.125f : -1e30f;
            sacc[j][1] = msk[c + 1] ? sacc[j][1] * 0.125f : -1e30f;
            sacc[j][2] = msk[c]     ? sacc[j][2] * 0.125f : -1e30f;
            sacc[j][3] = msk[c + 1] ? sacc[j][3] * 0.125f : -1e30f;
            tmax0 = fmaxf(tmax0, fmaxf(sacc[j][0], sacc[j][1]));
            tmax1 = fmaxf(tmax1, fmaxf(sacc[j][2], sacc[j][3]));
        }
        tmax0 = fmaxf(tmax0, __shfl_xor_sync(0xffffffffu, tmax0, 1));
        tmax0 = fmaxf(tmax0, __shfl_xor_sync(0xffffffffu, tmax0, 2));
        tmax1 = fmaxf(tmax1, __shfl_xor_sync(0xffffffffu, tmax1, 1));
        tmax1 = fmaxf(tmax1, __shfl_xor_sync(0xffffffffu, tmax1, 2));
        float mnew0 = fmaxf(mrow0, tmax0);
        float mnew1 = fmaxf(mrow1, tmax1);
        float alpha0 = (mrow0 == -INFINITY) ? 0.f : __expf(mrow0 - mnew0);
        float alpha1 = (mrow1 == -INFINITY) ? 0.f : __expf(mrow1 - mnew1);
        float rs0 = 0.f, rs1 = 0.f;
#pragma unroll
        for (int j = 0; j < 16; j++) {
            float p0 = __expf(sacc[j][0] - mnew0);
            float p1 = __expf(sacc[j][1] - mnew0);
            float p2 = __expf(sacc[j][2] - mnew1);
            float p3 = __expf(sacc[j][3] - mnew1);
            rs0 += p0 + p1; rs1 += p2 + p3;
            sacc[j][0] = p0; sacc[j][1] = p1; sacc[j][2] = p2; sacc[j][3] = p3;
        }
        rs0 += __shfl_xor_sync(0xffffffffu, rs0, 1);
        rs0 += __shfl_xor_sync(0xffffffffu, rs0, 2);
        rs1 += __shfl_xor_sync(0xffffffffu, rs1, 1);
        rs1 += __shfl_xor_sync(0xffffffffu, rs1, 2);
        lrow0 = lrow0 * alpha0 + rs0;
        lrow1 = lrow1 * alpha1 + rs1;
        mrow0 = mnew0; mrow1 = mnew1;
#pragma unroll
        for (int j = 0; j < 8; j++) {
            cacc[j][0] *= alpha0; cacc[j][1] *= alpha0;
            cacc[j][2] *= alpha1; cacc[j][3] *= alpha1;
        }
#pragma unroll
        for (int t = 0; t < 8; t++) {
            uint32_t pah[4];
            {
                float* s0 = sacc[2 * t]; float* s1 = sacc[2 * t + 1];
                pah[0] = pack_h2(s0[0], s0[1]);
                pah[1] = pack_h2(s0[2], s0[3]);
                pah[2] = pack_h2(s1[0], s1[1]);
                pah[3] = pack_h2(s1[2], s1[3]);
            }
            uint32_t vbh[16];
            int sub = t >> 2;
            int cgv = (t & 3) * 2 + bcgs;
#pragma unroll
            for (int prd = 0; prd < 4; prd++) {
                int row = prd * 16 + brow_b;
                uint32_t off = (uint32_t)(sub * 8192) + (uint32_t)(row * 128) +
                               (uint32_t)((cgv ^ (row & 7)) << 4);
                LDSM4(vbh + prd * 4, Vh + off);
            }
#pragma unroll
            for (int jd = 0; jd < 8; jd++) {
                uint32_t* rh = vbh + (jd >> 1) * 4 + (jd & 1) * 2;
                MMA_F16(cacc[jd], pah, rh);
            }
        }
        __syncthreads();
        if (tid == 0 && kb + 4 < 16) issue(s, kb + 4);
    }
    float inv0 = (lrow0 > 0.f) ? (1.f / lrow0) : 0.f;
    float inv1 = (lrow1 > 0.f) ? (1.f / lrow1) : 0.f;
    int r0 = wid * 16 + (ln >> 2);
    size_t tile = ((size_t)h * 16 + qb) * (size_t)TILE_B;
#pragma unroll
    for (int jd = 0; jd < 8; jd++) {
        uint32_t inoff = (uint32_t)(q2 * 2);
#pragma unroll
        for (int rr = 0; rr < 2; rr++) {
            int r = r0 + rr * 8;
            float v0 = cacc[jd][rr * 2] * (rr ? inv1 : inv0);
            float v1 = cacc[jd][rr * 2 + 1] * (rr ? inv1 : inv0);
            uint32_t off = (uint32_t)(r * 128) + (uint32_t)((jd ^ (r & 7)) << 4) + inoff;
            *(uint32_t*)((char*)Chi + tile + off) = pack_h2(v0, v1);
        }
    }
}

// ---------------- LayerNorm -> tiled fp16 directly ----------------------------
__global__ void ln_tile(const float* __restrict__ x, const float* __restrict__ w,
                        const float* __restrict__ b, __half* __restrict__ Hi) {
    int row = blockIdx.x;
    int tid = threadIdx.x;
    const float* xr = x + (size_t)row * D_MODEL;
    float4 v0 = *(const float4*)&xr[tid * 8];
    float4 v1 = *(const float4*)&xr[tid * 8 + 4];
    float xin[8] = {v0.x, v0.y, v0.z, v0.w, v1.x, v1.y, v1.z, v1.w};
    float s = 0.f, s2 = 0.f;
#pragma unroll
    for (int u = 0; u < 8; u++) { s += xin[u]; s2 += xin[u] * xin[u]; }
    __shared__ float r0s[256], r1s[256];
    r0s[tid] = s; r1s[tid] = s2;
    __syncthreads();
    for (int o = 128; o > 0; o >>= 1) {
        if (tid < o) { r0s[tid] += r0s[tid + o]; r1s[tid] += r1s[tid + o]; }
        __syncthreads();
    }
    float mean = r0s[0] * (1.0f / D_MODEL);
    float var  = r1s[0] * (1.0f / D_MODEL) - mean * mean;
    float inv  = rsqrtf(var + 1e-5f);
    int kt = tid >> 3, c8 = tid & 7;
    int mt = row >> 7, r = row & 127;
    size_t tile = ((size_t)kt * 16 + mt) * (size_t)TILE_B;
    uint32_t off = (uint32_t)(r * 128) + (uint32_t)((c8 ^ (r & 7)) << 4);
    __half h8[8];
#pragma unroll
    for (int u = 0; u < 8; u++)
        h8[u] = __float2half_rn((xin[u] - mean) * inv * w[tid * 8 + u] + b[tid * 8 + u]);
    *(uint4*)((char*)Hi + tile + off) = *(uint4*)h8;
}

// ---------------- V fp32 -> transposed fp16 tiles [64 d][128 keys] -----------
__global__ void conv_vt(const float* __restrict__ src, __half* __restrict__ Hi) {
    __shared__ float s[128][65];
    int sbk = blockIdx.x, kvh = blockIdx.y;
    int tid = threadIdx.x;
    for (int t = tid; t < 128 * 16; t += 256) {
        int r = t >> 4, c4 = (t & 15) * 4;
        float4 v = *(const float4*)&src[(size_t)(sbk * 128 + r) * QKV_N + 2560 + kvh * 64 + c4];
        s[r][c4] = v.x; s[r][c4 + 1] = v.y; s[r][c4 + 2] = v.z; s[r][c4 + 3] = v.w;
    }
    __syncthreads();
    size_t tile = ((size_t)kvh * 16 + sbk) * (size_t)TILE_B;
    for (int t = tid; t < 1024; t += 256) {
        int d = t >> 4, kc8 = t & 15;
        int sub = kc8 >> 3, c8 = kc8 & 7;
        __half h8[8];
#pragma unroll
        for (int u = 0; u < 8; u++)
            h8[u] = __float2half_rn(s[(kc8 & 7) * 8 + sub * 64 + u][d]);
        uint32_t off = (uint32_t)(sub * 8192) + (uint32_t)(d * 128) +
                       (uint32_t)((c8 ^ (d & 7)) << 4);
        *(uint4*)((char*)Hi + tile + off) = *(uint4*)h8;
    }
}

// ---------------- fp32 weight [K,N] -> tiled transposed fp16 -----------------
__global__ void conv_w(const float* __restrict__ W, __half* __restrict__ Hi,
                       int K, int Nsrc, int nt_off, int NT_total) {
    __shared__ float s[128][65];
    int kt = blockIdx.x, nt = blockIdx.y;
    int tid = threadIdx.x;
    for (int t = tid; t < 64 * 32; t += 256) {
        int i = t >> 5, j4 = (t & 31) * 4;
        float4 v = *(const float4*)&W[((size_t)kt * 64 + i) * Nsrc + (size_t)nt * 128 + j4];
        s[j4 + 0][i] = v.x; s[j4 + 1][i] = v.y; s[j4 + 2][i] = v.z; s[j4 + 3][i] = v.w;
    }
    __syncthreads();
    size_t tile = ((size_t)kt * NT_total + (nt_off + nt)) * TILE_B;
    for (int t = tid; t < 1024; t += 256) {
        int r = t >> 3, c8 = t & 7;
        __half h8[8];
#pragma unroll
        for (int u = 0; u < 8; u++)
            h8[u] = __float2half_rn(s[r][c8 * 8 + u]);
        uint32_t off = (uint32_t)(r * 128) + (uint32_t)((c8 ^ (r & 7)) << 4);
        *(uint4*)((char*)Hi + tile + off) = *(uint4*)h8;
    }
}

// ---------------- w1/w3 -> interleaved tiles (rows 0-63 = w1, 64-127 = w3) ---
__global__ void conv_w13(const float* __restrict__ W, __half* __restrict__ Hi,
                         int rowoff) {
    __shared__ float s[64][65];
    int kt = blockIdx.x, nt = blockIdx.y;      // kt over 32, nt over 88
    int tid = threadIdx.x;
    for (int t = tid; t < 64 * 16; t += 256) {
        int i = t >> 4, j4 = (t & 15) * 4;
        float4 v = *(const float4*)&W[((size_t)kt * 64 + i) * HID + (size_t)nt * 64 + j4];
        s[j4 + 0][i] = v.x; s[j4 + 1][i] = v.y; s[j4 + 2][i] = v.z; s[j4 + 3][i] = v.w;
    }
    __syncthreads();
    size_t tile = ((size_t)kt * 88 + nt) * (size_t)TILE_B;
    for (int t = tid; t < 512; t += 256) {
        int rr = t >> 3, c8 = t & 7;
        int r = rowoff + rr;
        __half h8[8];
#pragma unroll
        for (int u = 0; u < 8; u++)
            h8[u] = __float2half_rn(s[rr][c8 * 8 + u]);
        uint32_t off = (uint32_t)(r * 128) + (uint32_t)((c8 ^ (r & 7)) << 4);
        *(uint4*)((char*)Hi + tile + off) = *(uint4*)h8;
    }
}

// ---------------- launch -----------------------------------------------------
extern "C" void kernel_launch(void* const* d_in, const int* in_sizes, int n_in,
                              void* d_out, int out_size) {
    const float* x    = (const float*)d_in[0];
    const int*   mask = (const int*)  d_in[1];
    const float* wq   = (const float*)d_in[2];
    const float* wk   = (const float*)d_in[3];
    const float* wv   = (const float*)d_in[4];
    const float* wo   = (const float*)d_in[5];
    const float* w1   = (const float*)d_in[6];
    const float* w2   = (const float*)d_in[7];
    const float* w3   = (const float*)d_in[8];
    const float* ln1w = (const float*)d_in[9];
    const float* ln1b = (const float*)d_in[10];
    const float* ln2w = (const float*)d_in[11];
    const float* ln2b = (const float*)d_in[12];
    float* out = (float*)d_out;

    float *qkv, *x1;
    cudaGetSymbolAddress((void**)&qkv, g_qkv);
    cudaGetSymbolAddress((void**)&x1,  g_x1);

    __half *hhi, *chi, *ghi;
    __half *wqkvh, *woh, *w13h, *w2h;
    __half *qah, *kah, *vah;
    cudaGetSymbolAddress((void**)&hhi, t_h_hi);
    cudaGetSymbolAddress((void**)&chi, t_ctx_hi);
    cudaGetSymbolAddress((void**)&ghi, t_g_hi);
    cudaGetSymbolAddress((void**)&wqkvh, t_wqkv_hi);
    cudaGetSymbolAddress((void**)&woh, t_wo_hi);
    cudaGetSymbolAddress((void**)&w13h, t_w13_hi);
    cudaGetSymbolAddress((void**)&w2h, t_w2_hi);
    cudaGetSymbolAddress((void**)&qah, t_qat_hi);
    cudaGetSymbolAddress((void**)&kah, t_kat_hi);
    cudaGetSymbolAddress((void**)&vah, t_vat_hi);

    cudaFuncSetAttribute(mma_gemm, cudaFuncAttributeMaxDynamicSharedMemorySize, GEMM_SMEM);
    cudaFuncSetAttribute(attn_mma, cudaFuncAttributeMaxDynamicSharedMemorySize, ATT_SMEM);

    // weights -> tiled fp16
    conv_w<<<dim3(D_MODEL / 64, 16), 256>>>(wq, wqkvh, D_MODEL, D_MODEL, 0,  24);
    conv_w<<<dim3(D_MODEL / 64, 4),  256>>>(wk, wqkvh, D_MODEL, 512,     16, 24);
    conv_w<<<dim3(D_MODEL / 64, 4),  256>>>(wv, wqkvh, D_MODEL, 512,     20, 24);
    conv_w<<<dim3(D_MODEL / 64, 16), 256>>>(wo, woh,   D_MODEL, D_MODEL, 0,  16);
    conv_w13<<<dim3(D_MODEL / 64, 88), 256>>>(w1, w13h, 0);
    conv_w13<<<dim3(D_MODEL / 64, 88), 256>>>(w3, w13h, 64);
    conv_w<<<dim3(HID / 64,     16), 256>>>(w2, w2h,   HID,     D_MODEL, 0,  16);

    // h tiles = LN1(x)
    ln_tile<<<S_LEN, 256>>>(x, ln1w, ln1b, hhi);

    // qkv GEMM: rope Q/K -> attention tiles; V -> fp32
    mma_gemm<<<dim3(QKV_N / 128, S_LEN / 128), 256, GEMM_SMEM>>>(hhi, wqkvh,
        nullptr, qkv, S_LEN, QKV_N, D_MODEL, 1, qah, kah);

    conv_vt<<<dim3(16, NKV), 256>>>(qkv, vah);

    // attention -> ctx tiles
    attn_mma<<<dim3(S_LEN / 128, NH), 256, ATT_SMEM>>>(qah, kah, vah, mask, chi);

    // x1 = x + ctx @ wo (fp32)
    mma_gemm<<<dim3(D_MODEL / 128, S_LEN / 128), 256, GEMM_SMEM>>>(chi, woh,
        x, x1, S_LEN, D_MODEL, D_MODEL, 0, nullptr, nullptr);

    // h tiles = LN2(x1)
    ln_tile<<<S_LEN, 256>>>(x1, ln2w, ln2b, hhi);

    // fused: gb tiles = silu(h @ w1) * (h @ w3)
    mma_gemm<<<dim3(W13_N / 128, S_LEN / 128), 256, GEMM_SMEM>>>(hhi, w13h,
        nullptr, nullptr, S_LEN, W13_N, D_MODEL, 3, ghi, nullptr);

    // out = x1 + gb @ w2
    mma_gemm<<<dim3(D_MODEL / 128, S_LEN / 128), 256, GEMM_SMEM>>>(ghi, w2h,
        x1, out, S_LEN, D_MODEL, HID, 0, nullptr, nullptr);
}

// round 17
// speedup vs baseline: 1.3994x; 1.3994x over previous
#include <cuda_runtime.h>
#include <cuda_fp16.h>
#include <cstdint>
#include <math.h>

#define S_LEN   2048
#define D_MODEL 2048
#define HID     5632
#define NH      32
#define NKV     8
#define HD      64
#define QKV_N   3072        // 2048 q | 512 k | 512 v
#define W13_N   11264       // 5632 g1 | 5632 g3 (interleaved 64/64 per 128-tile)
#define TILE_B  16384

// ---------------- fp32 scratch ------------------------------------------------
__device__ __align__(1024) float g_x1 [S_LEN * D_MODEL];

// ---------------- fp16 scratch ------------------------------------------------
__device__ __align__(1024) __half t_h_hi  [S_LEN * D_MODEL];
__device__ __align__(1024) __half t_ctx_hi[S_LEN * D_MODEL];
__device__ __align__(1024) __half t_g_hi  [S_LEN * HID];
__device__ __align__(1024) __half t_wqkv_hi[QKV_N * D_MODEL];
__device__ __align__(1024) __half t_wo_hi [D_MODEL * D_MODEL];
__device__ __align__(1024) __half t_w13_hi[W13_N * D_MODEL];
__device__ __align__(1024) __half t_w2_hi [D_MODEL * HID];
__device__ __align__(1024) __half t_qat_hi[NH  * 16 * 8192];
__device__ __align__(1024) __half t_kat_hi[NKV * 16 * 8192];
__device__ __align__(1024) __half t_vat_hi[NKV * 16 * 8192];

// ---------------- PTX helpers (baseline PTX only) -----------------------------
__device__ __forceinline__ uint32_t smem_u32(const void* p) {
    uint32_t a;
    asm("{ .reg .u64 t; cvta.to.shared.u64 t, %1; cvt.u32.u64 %0, t; }" : "=r"(a) : "l"(p));
    return a;
}
#define MBAR_INIT(a, c) asm volatile("mbarrier.init.shared.b64 [%0], %1;" :: "r"(a), "r"(c) : "memory")
#define MBAR_EXPECT(a, b) asm volatile("mbarrier.arrive.expect_tx.shared.b64 _, [%0], %1;" :: "r"(a), "r"(b) : "memory")
__device__ __forceinline__ void mbar_wait(uint32_t mbar, uint32_t parity) {
    asm volatile(
        "{\n\t.reg .pred P1;\n\t"
        "W_%=:\n\t"
        "mbarrier.try_wait.parity.acquire.cta.shared::cta.b64 P1, [%0], %1, 0x989680;\n\t"
        "@P1 bra.uni D_%=;\n\t"
        "bra.uni W_%=;\n\t"
        "D_%=:\n\t}"
        :: "r"(mbar), "r"(parity) : "memory");
}
__device__ __forceinline__ void bulk_g2s(uint32_t dst, const void* src, uint32_t bytes, uint32_t mbar) {
    asm volatile("cp.async.bulk.shared::cta.global.mbarrier::complete_tx::bytes [%0], [%1], %2, [%3];"
        :: "r"(dst), "l"(src), "r"(bytes), "r"(mbar) : "memory");
}
#define LDSM4(r, a) \
    asm volatile("ldmatrix.sync.aligned.m8n8.x4.shared.b16 {%0,%1,%2,%3}, [%4];" \
        : "=r"((r)[0]), "=r"((r)[1]), "=r"((r)[2]), "=r"((r)[3]) : "r"(a))
#define MMA_F16(d, a, b) \
    asm volatile("mma.sync.aligned.m16n8k16.row.col.f32.f16.f16.f32 " \
        "{%0,%1,%2,%3}, {%4,%5,%6,%7}, {%8,%9}, {%0,%1,%2,%3};" \
        : "+f"((d)[0]), "+f"((d)[1]), "+f"((d)[2]), "+f"((d)[3]) \
        : "r"((a)[0]), "r"((a)[1]), "r"((a)[2]), "r"((a)[3]), "r"((b)[0]), "r"((b)[1]))

__device__ __forceinline__ uint32_t pack_h2(float a, float b) {
    __half2 t = __floats2half2_rn(a, b);
    return *(uint32_t*)&t;
}

// ---------------- mma.sync GEMM (4-stage pipeline, single-pass fp16) ---------
// mode 0: C fp32 (+R)
// mode 1: qkv — rope Q (-> PQ), K (-> PK); V -> transposed tiles (PV)
// mode 3: fused W13 -> silu(g1)*g3 -> gb A-tiles (PQ)
__global__ void __launch_bounds__(256, 1) mma_gemm(
    const __half* __restrict__ Ahi, const __half* __restrict__ Bhi,
    const float* __restrict__ R, float* __restrict__ C, int M, int N, int K, int mode,
    __half* __restrict__ PQ, __half* __restrict__ PK, __half* __restrict__ PV)
{
    extern __shared__ char smem[];
    uint32_t sb = smem_u32(smem);
    int tid = threadIdx.x, wid = tid >> 5, ln = tid & 31;
    int wm = wid >> 2, wn = wid & 3;
    int mt = blockIdx.y, nt = blockIdx.x;
    int MT = M >> 7, NT = N >> 7, KTt = K >> 6;
    uint32_t mb0 = sb + 4 * 2 * TILE_B;

    if (tid == 0) {
        MBAR_INIT(mb0, 1); MBAR_INIT(mb0 + 8, 1);
        MBAR_INIT(mb0 + 16, 1); MBAR_INIT(mb0 + 24, 1);
    }
    __syncthreads();

    auto issue = [&](int s, int kt) {
        uint32_t mb = mb0 + s * 8;
        uint32_t dst = sb + s * (2 * TILE_B);
        size_t aoff = ((size_t)kt * MT + mt) * (size_t)(128 * 64);
        size_t boff = ((size_t)kt * NT + nt) * (size_t)(128 * 64);
        MBAR_EXPECT(mb, 2 * TILE_B);
        bulk_g2s(dst,          Ahi + aoff, TILE_B, mb);
        bulk_g2s(dst + TILE_B, Bhi + boff, TILE_B, mb);
    };
    if (tid == 0) {
        issue(0, 0);
        if (KTt > 1) issue(1, 1);
        if (KTt > 2) issue(2, 2);
        if (KTt > 3) issue(3, 3);
    }

    float acc[4][4][4];
#pragma unroll
    for (int i = 0; i < 4; i++)
#pragma unroll
        for (int j = 0; j < 4; j++)
#pragma unroll
            for (int r = 0; r < 4; r++) acc[i][j][r] = 0.f;

    int arow0 = wm * 64 + (ln & 7) + ((ln & 8) ? 8 : 0);
    int acgs  = (ln >> 4) & 1;
    int brow0 = wn * 32 + (ln & 7) + ((ln & 16) ? 8 : 0);
    int bcgs  = (ln >> 3) & 1;

    for (int kt = 0; kt < KTt; kt++) {
        int s = kt & 3, ph = (kt >> 2) & 1;
        mbar_wait(mb0 + s * 8, ph);
        uint32_t st = sb + s * (2 * TILE_B);
        uint32_t Ah = st, Bh = st + TILE_B;
#pragma unroll
        for (int ks = 0; ks < 4; ks++) {
            int acg = ks * 2 + acgs;
            int bcg = ks * 2 + bcgs;
            uint32_t ahr[16], bhr[8];
#pragma unroll
            for (int fm = 0; fm < 4; fm++) {
                int row = arow0 + fm * 16;
                uint32_t off = (uint32_t)(row * 128) + (uint32_t)((acg ^ (row & 7)) << 4);
                LDSM4(ahr + fm * 4, Ah + off);
            }
#pragma unroll
            for (int pr = 0; pr < 2; pr++) {
                int row = brow0 + pr * 16;
                uint32_t off = (uint32_t)(row * 128) + (uint32_t)((bcg ^ (row & 7)) << 4);
                LDSM4(bhr + pr * 4, Bh + off);
            }
#pragma unroll
            for (int fm = 0; fm < 4; fm++)
#pragma unroll
                for (int fn = 0; fn < 4; fn++)
                    MMA_F16(acc[fm][fn], ahr + fm * 4, bhr + fn * 2);
        }
        __syncthreads();
        if (tid == 0 && kt + 4 < KTt) issue(s, kt + 4);
    }

    int qr = ln >> 2, qc = ln & 3;

    if (mode == 3) {
        // stage fp32 accs to smem [128][132], then silu-combine -> gb A-tile
        float* sf = (float*)smem;
#pragma unroll
        for (int fm = 0; fm < 4; fm++) {
            int rl = wm * 64 + fm * 16 + qr;
#pragma unroll
            for (int fn = 0; fn < 4; fn++) {
                int col = wn * 32 + fn * 8 + 2 * qc;
                sf[rl * 132 + col]           = acc[fm][fn][0];
                sf[rl * 132 + col + 1]       = acc[fm][fn][1];
                sf[(rl + 8) * 132 + col]     = acc[fm][fn][2];
                sf[(rl + 8) * 132 + col + 1] = acc[fm][fn][3];
            }
        }
        __syncthreads();
        size_t tile = ((size_t)nt * MT + mt) * (size_t)TILE_B;
#pragma unroll
        for (int i = 0; i < 4; i++) {
            int ch = tid + 256 * i;         // 0..1023
            int r = ch >> 3, c8 = ch & 7;
            __half h8[8];
#pragma unroll
            for (int u = 0; u < 8; u++) {
                float a = sf[r * 132 + c8 * 8 + u];
                float c = sf[r * 132 + 64 + c8 * 8 + u];
                float sig = 1.0f / (1.0f + expf(-a));
                h8[u] = __float2half_rn(a * sig * c);
            }
            uint32_t off = (uint32_t)(r * 128) + (uint32_t)((c8 ^ (r & 7)) << 4);
            *(uint4*)((char*)PQ + tile + off) = *(uint4*)h8;
        }
        return;
    }

    float freqs[4];
    if (mode == 1) {
#pragma unroll
        for (int fn = 0; fn < 4; fn++) {
            int col = nt * 128 + wn * 32 + fn * 8 + 2 * qc;
            int i = (col & 63) >> 1;
            freqs[fn] = 1.0f / powf(10000.0f, (2.0f * (float)i) / 64.0f);
        }
    }

#pragma unroll
    for (int fm = 0; fm < 4; fm++) {
        int row0 = mt * 128 + wm * 64 + fm * 16 + qr;
#pragma unroll
        for (int fn = 0; fn < 4; fn++) {
            int col = nt * 128 + wn * 32 + fn * 8 + 2 * qc;
            if (mode == 0) {
                size_t i0 = (size_t)row0 * N + col;
                size_t i1 = (size_t)(row0 + 8) * N + col;
                float2 v0 = make_float2(acc[fm][fn][0], acc[fm][fn][1]);
                float2 v1 = make_float2(acc[fm][fn][2], acc[fm][fn][3]);
                if (R) {
                    float2 r0 = *(const float2*)&R[i0];
                    float2 r1 = *(const float2*)&R[i1];
                    v0.x += r0.x; v0.y += r0.y; v1.x += r1.x; v1.y += r1.y;
                }
                *(float2*)&C[i0] = v0;
                *(float2*)&C[i1] = v1;
            } else {   // mode 1: qkv
                if (col >= 2560) {
                    // V -> transposed fp16 tiles directly (same fp32->fp16 value
                    // as the old g_qkv round-trip; layout matches conv_vt)
                    int d   = (col - 2560) & 63;
                    int kvh = (col - 2560) >> 6;
#pragma unroll
                    for (int rr = 0; rr < 2; rr++) {
                        int row = row0 + rr * 8;
                        int keyl = row & 127;
                        size_t tile = ((size_t)kvh * 16 + (row >> 7)) * (size_t)TILE_B;
                        uint32_t base = (uint32_t)((keyl >> 6) * 8192) + (uint32_t)((keyl & 7) * 2);
                        int c8k = (keyl >> 3) & 7;
                        uint32_t off0 = base + (uint32_t)(d * 128) +
                                        (uint32_t)((c8k ^ (d & 7)) << 4);
                        uint32_t off1 = base + (uint32_t)((d + 1) * 128) +
                                        (uint32_t)((c8k ^ ((d + 1) & 7)) << 4);
                        *(__half*)((char*)PV + tile + off0) = __float2half_rn(acc[fm][fn][rr * 2]);
                        *(__half*)((char*)PV + tile + off1) = __float2half_rn(acc[fm][fn][rr * 2 + 1]);
                    }
                } else {
                    float freq = freqs[fn];
                    int isq = (col < 2048);
                    int head = isq ? (col >> 6) : ((col - 2048) >> 6);
                    __half* Hp = isq ? PQ : PK;
                    int c8 = (col & 63) >> 3;
                    uint32_t inoff = (uint32_t)((col & 7) * 2);
#pragma unroll
                    for (int rr = 0; rr < 2; rr++) {
                        int row = row0 + rr * 8;
                        float v0 = acc[fm][fn][rr * 2], v1 = acc[fm][fn][rr * 2 + 1];
                        float sn, cs; sincosf((float)row * freq, &sn, &cs);
                        float orr = v0 * cs - v1 * sn;
                        float oii = v0 * sn + v1 * cs;
                        int r = row & 127;
                        size_t tile = ((size_t)head * 16 + (row >> 7)) * (size_t)TILE_B;
                        uint32_t off = (uint32_t)(r * 128) + (uint32_t)((c8 ^ (r & 7)) << 4) + inoff;
                        *(uint32_t*)((char*)Hp + tile + off) = pack_h2(orr, oii);
                    }
                }
            }
        }
    }
}
#define GEMM_SMEM (4 * 2 * TILE_B + 64)

// ---------------- tensorized flash attention (single-pass fp16) --------------
#define ATT_SQ    0u
#define ATT_SMSK  16384u
#define ATT_SST   24576u
#define ATT_MB    (24576u + 131072u)
#define ATT_SMEM  (24576 + 131072 + 64)
__global__ void __launch_bounds__(256, 1) attn_mma(
    const __half* __restrict__ Qhi,
    const __half* __restrict__ Khi, const __half* __restrict__ Vhi,
    const int* __restrict__ mask,
    __half* __restrict__ Chi)
{
    extern __shared__ char smem[];
    uint32_t sb = smem_u32(smem);
    int tid = threadIdx.x, wid = tid >> 5, ln = tid & 31;
    int qb = blockIdx.x, h = blockIdx.y;
    int kvh = h >> 2;
    int q2 = (ln & 3) * 2;

    int* msk = (int*)(smem + ATT_SMSK);
    for (int i = tid; i < S_LEN; i += 256) msk[i] = mask[i];
    {
        const uint4* qs0 = (const uint4*)(Qhi + ((size_t)h * 16 + qb) * 8192);
        uint4* qd0 = (uint4*)(smem + ATT_SQ);
        for (int i = tid; i < 1024; i += 256) qd0[i] = qs0[i];
    }
    uint32_t mb0 = sb + ATT_MB;
    if (tid == 0) {
        MBAR_INIT(mb0, 1); MBAR_INIT(mb0 + 8, 1);
        MBAR_INIT(mb0 + 16, 1); MBAR_INIT(mb0 + 24, 1);
    }
    __syncthreads();

    auto issue = [&](int s, int kb) {
        uint32_t mb = mb0 + s * 8;
        uint32_t dst = sb + ATT_SST + s * 32768;
        size_t ko = ((size_t)kvh * 16 + kb) * 8192;
        MBAR_EXPECT(mb, 32768);
        bulk_g2s(dst,         Khi + ko, 16384, mb);
        bulk_g2s(dst + 16384, Vhi + ko, 16384, mb);
    };
    if (tid == 0) { issue(0, 0); issue(1, 1); issue(2, 2); issue(3, 3); }

    uint32_t qh[4][4];
    {
        int arow0 = wid * 16 + (ln & 7) + ((ln & 8) ? 8 : 0);
        int acgs = (ln >> 4) & 1;
#pragma unroll
        for (int ks = 0; ks < 4; ks++) {
            int cg = ks * 2 + acgs;
            uint32_t off = (uint32_t)(arow0 * 128) + (uint32_t)((cg ^ (arow0 & 7)) << 4);
            LDSM4(qh[ks], sb + ATT_SQ + off);
        }
    }

    float mrow0 = -INFINITY, mrow1 = -INFINITY, lrow0 = 0.f, lrow1 = 0.f;
    float cacc[8][4];
#pragma unroll
    for (int j = 0; j < 8; j++)
#pragma unroll
        for (int r = 0; r < 4; r++) cacc[j][r] = 0.f;

    int brow_b = (ln & 7) + ((ln & 16) ? 8 : 0);
    int bcgs = (ln >> 3) & 1;

    for (int kb = 0; kb < 16; kb++) {
        int s = kb & 3, ph = (kb >> 2) & 1;
        mbar_wait(mb0 + s * 8, ph);
        uint32_t st = sb + ATT_SST + s * 32768;
        uint32_t Kh = st, Vh = st + 16384;

        float sacc[16][4];
#pragma unroll
        for (int j = 0; j < 16; j++)
#pragma unroll
            for (int r = 0; r < 4; r++) sacc[j][r] = 0.f;
#pragma unroll
        for (int nj = 0; nj < 4; nj++) {
#pragma unroll
            for (int ks = 0; ks < 4; ks++) {
                uint32_t bh[8];
                int cg = ks * 2 + bcgs;
#pragma unroll
                for (int pr = 0; pr < 2; pr++) {
                    int row = nj * 32 + pr * 16 + brow_b;
                    uint32_t off = (uint32_t)(row * 128) + (uint32_t)((cg ^ (row & 7)) << 4);
                    LDSM4(bh + pr * 4, Kh + off);
                }
#pragma unroll
                for (int nt = 0; nt < 4; nt++) {
                    float* d = sacc[nj * 4 + nt];
                    uint32_t* rh = bh + (nt >> 1) * 4 + (nt & 1) * 2;
                    MMA_F16(d, qh[ks], rh);
                }
            }
        }
        float tmax0 = -INFINITY, tmax1 = -INFINITY;
#pragma unroll
        for (int j = 0; j < 16; j++) {
            int c = kb * 128 + 8 * j + q2;
            sacc[j][0] = msk[c]     ? sacc[j][0] * 0.125f : -1e30f;
            sacc[j][1] = msk[c + 1] ? sacc[j][1] * 0.125f : -1e30f;
            sacc[j][2] = msk[c]     ? sacc[j][2] * 0.125f : -1e30f;
            sacc[j][3] = msk[c + 1] ? sacc[j][3] * 0.125f : -1e30f;
            tmax0 = fmaxf(tmax0, fmaxf(sacc[j][0], sacc[j][1]));
            tmax1 = fmaxf(tmax1, fmaxf(sacc[j][2], sacc[j][3]));
        }
        tmax0 = fmaxf(tmax0, __shfl_xor_sync(0xffffffffu, tmax0, 1));
        tmax0 = fmaxf(tmax0, __shfl_xor_sync(0xffffffffu, tmax0, 2));
        tmax1 = fmaxf(tmax1, __shfl_xor_sync(0xffffffffu, tmax1, 1));
        tmax1 = fmaxf(tmax1, __shfl_xor_sync(0xffffffffu, tmax1, 2));
        float mnew0 = fmaxf(mrow0, tmax0);
        float mnew1 = fmaxf(mrow1, tmax1);
        float alpha0 = (mrow0 == -INFINITY) ? 0.f : __expf(mrow0 - mnew0);
        float alpha1 = (mrow1 == -INFINITY) ? 0.f : __expf(mrow1 - mnew1);
        float rs0 = 0.f, rs1 = 0.f;
#pragma unroll
        for (int j = 0; j < 16; j++) {
            float p0 = __expf(sacc[j][0] - mnew0);
            float p1 = __expf(sacc[j][1] - mnew0);
            float p2 = __expf(sacc[j][2] - mnew1);
            float p3 = __expf(sacc[j][3] - mnew1);
            rs0 += p0 + p1; rs1 += p2 + p3;
            sacc[j][0] = p0; sacc[j][1] = p1; sacc[j][2] = p2; sacc[j][3] = p3;
        }
        rs0 += __shfl_xor_sync(0xffffffffu, rs0, 1);
        rs0 += __shfl_xor_sync(0xffffffffu, rs0, 2);
        rs1 += __shfl_xor_sync(0xffffffffu, rs1, 1);
        rs1 += __shfl_xor_sync(0xffffffffu, rs1, 2);
        lrow0 = lrow0 * alpha0 + rs0;
        lrow1 = lrow1 * alpha1 + rs1;
        mrow0 = mnew0; mrow1 = mnew1;
#pragma unroll
        for (int j = 0; j < 8; j++) {
            cacc[j][0] *= alpha0; cacc[j][1] *= alpha0;
            cacc[j][2] *= alpha1; cacc[j][3] *= alpha1;
        }
#pragma unroll
        for (int t = 0; t < 8; t++) {
            uint32_t pah[4];
            {
                float* s0 = sacc[2 * t]; float* s1 = sacc[2 * t + 1];
                pah[0] = pack_h2(s0[0], s0[1]);
                pah[1] = pack_h2(s0[2], s0[3]);
                pah[2] = pack_h2(s1[0], s1[1]);
                pah[3] = pack_h2(s1[2], s1[3]);
            }
            uint32_t vbh[16];
            int sub = t >> 2;
            int cgv = (t & 3) * 2 + bcgs;
#pragma unroll
            for (int prd = 0; prd < 4; prd++) {
                int row = prd * 16 + brow_b;
                uint32_t off = (uint32_t)(sub * 8192) + (uint32_t)(row * 128) +
                               (uint32_t)((cgv ^ (row & 7)) << 4);
                LDSM4(vbh + prd * 4, Vh + off);
            }
#pragma unroll
            for (int jd = 0; jd < 8; jd++) {
                uint32_t* rh = vbh + (jd >> 1) * 4 + (jd & 1) * 2;
                MMA_F16(cacc[jd], pah, rh);
            }
        }
        __syncthreads();
        if (tid == 0 && kb + 4 < 16) issue(s, kb + 4);
    }
    float inv0 = (lrow0 > 0.f) ? (1.f / lrow0) : 0.f;
    float inv1 = (lrow1 > 0.f) ? (1.f / lrow1) : 0.f;
    int r0 = wid * 16 + (ln >> 2);
    size_t tile = ((size_t)h * 16 + qb) * (size_t)TILE_B;
#pragma unroll
    for (int jd = 0; jd < 8; jd++) {
        uint32_t inoff = (uint32_t)(q2 * 2);
#pragma unroll
        for (int rr = 0; rr < 2; rr++) {
            int r = r0 + rr * 8;
            float v0 = cacc[jd][rr * 2] * (rr ? inv1 : inv0);
            float v1 = cacc[jd][rr * 2 + 1] * (rr ? inv1 : inv0);
            uint32_t off = (uint32_t)(r * 128) + (uint32_t)((jd ^ (r & 7)) << 4) + inoff;
            *(uint32_t*)((char*)Chi + tile + off) = pack_h2(v0, v1);
        }
    }
}

// ---------------- LayerNorm -> tiled fp16 directly ----------------------------
__global__ void ln_tile(const float* __restrict__ x, const float* __restrict__ w,
                        const float* __restrict__ b, __half* __restrict__ Hi) {
    int row = blockIdx.x;
    int tid = threadIdx.x;
    const float* xr = x + (size_t)row * D_MODEL;
    float4 v0 = *(const float4*)&xr[tid * 8];
    float4 v1 = *(const float4*)&xr[tid * 8 + 4];
    float xin[8] = {v0.x, v0.y, v0.z, v0.w, v1.x, v1.y, v1.z, v1.w};
    float s = 0.f, s2 = 0.f;
#pragma unroll
    for (int u = 0; u < 8; u++) { s += xin[u]; s2 += xin[u] * xin[u]; }
    __shared__ float r0s[256], r1s[256];
    r0s[tid] = s; r1s[tid] = s2;
    __syncthreads();
    for (int o = 128; o > 0; o >>= 1) {
        if (tid < o) { r0s[tid] += r0s[tid + o]; r1s[tid] += r1s[tid + o]; }
        __syncthreads();
    }
    float mean = r0s[0] * (1.0f / D_MODEL);
    float var  = r1s[0] * (1.0f / D_MODEL) - mean * mean;
    float inv  = rsqrtf(var + 1e-5f);
    int kt = tid >> 3, c8 = tid & 7;
    int mt = row >> 7, r = row & 127;
    size_t tile = ((size_t)kt * 16 + mt) * (size_t)TILE_B;
    uint32_t off = (uint32_t)(r * 128) + (uint32_t)((c8 ^ (r & 7)) << 4);
    __half h8[8];
#pragma unroll
    for (int u = 0; u < 8; u++)
        h8[u] = __float2half_rn((xin[u] - mean) * inv * w[tid * 8 + u] + b[tid * 8 + u]);
    *(uint4*)((char*)Hi + tile + off) = *(uint4*)h8;
}

// ---------------- fp32 weight [K,N] -> tiled transposed fp16 -----------------
__global__ void conv_w(const float* __restrict__ W, __half* __restrict__ Hi,
                       int K, int Nsrc, int nt_off, int NT_total) {
    __shared__ float s[128][65];
    int kt = blockIdx.x, nt = blockIdx.y;
    int tid = threadIdx.x;
    for (int t = tid; t < 64 * 32; t += 256) {
        int i = t >> 5, j4 = (t & 31) * 4;
        float4 v = *(const float4*)&W[((size_t)kt * 64 + i) * Nsrc + (size_t)nt * 128 + j4];
        s[j4 + 0][i] = v.x; s[j4 + 1][i] = v.y; s[j4 + 2][i] = v.z; s[j4 + 3][i] = v.w;
    }
    __syncthreads();
    size_t tile = ((size_t)kt * NT_total + (nt_off + nt)) * TILE_B;
    for (int t = tid; t < 1024; t += 256) {
        int r = t >> 3, c8 = t & 7;
        __half h8[8];
#pragma unroll
        for (int u = 0; u < 8; u++)
            h8[u] = __float2half_rn(s[r][c8 * 8 + u]);
        uint32_t off = (uint32_t)(r * 128) + (uint32_t)((c8 ^ (r & 7)) << 4);
        *(uint4*)((char*)Hi + tile + off) = *(uint4*)h8;
    }
}

// ---------------- w1/w3 -> interleaved tiles (rows 0-63 = w1, 64-127 = w3) ---
__global__ void conv_w13(const float* __restrict__ W, __half* __restrict__ Hi,
                         int rowoff) {
    __shared__ float s[64][65];
    int kt = blockIdx.x, nt = blockIdx.y;      // kt over 32, nt over 88
    int tid = threadIdx.x;
    for (int t = tid; t < 64 * 16; t += 256) {
        int i = t >> 4, j4 = (t & 15) * 4;
        float4 v = *(const float4*)&W[((size_t)kt * 64 + i) * HID + (size_t)nt * 64 + j4];
        s[j4 + 0][i] = v.x; s[j4 + 1][i] = v.y; s[j4 + 2][i] = v.z; s[j4 + 3][i] = v.w;
    }
    __syncthreads();
    size_t tile = ((size_t)kt * 88 + nt) * (size_t)TILE_B;
    for (int t = tid; t < 512; t += 256) {
        int rr = t >> 3, c8 = t & 7;
        int r = rowoff + rr;
        __half h8[8];
#pragma unroll
        for (int u = 0; u < 8; u++)
            h8[u] = __float2half_rn(s[rr][c8 * 8 + u]);
        uint32_t off = (uint32_t)(r * 128) + (uint32_t)((c8 ^ (r & 7)) << 4);
        *(uint4*)((char*)Hi + tile + off) = *(uint4*)h8;
    }
}

// ---------------- launch -----------------------------------------------------
extern "C" void kernel_launch(void* const* d_in, const int* in_sizes, int n_in,
                              void* d_out, int out_size) {
    const float* x    = (const float*)d_in[0];
    const int*   mask = (const int*)  d_in[1];
    const float* wq   = (const float*)d_in[2];
    const float* wk   = (const float*)d_in[3];
    const float* wv   = (const float*)d_in[4];
    const float* wo   = (const float*)d_in[5];
    const float* w1   = (const float*)d_in[6];
    const float* w2   = (const float*)d_in[7];
    const float* w3   = (const float*)d_in[8];
    const float* ln1w = (const float*)d_in[9];
    const float* ln1b = (const float*)d_in[10];
    const float* ln2w = (const float*)d_in[11];
    const float* ln2b = (const float*)d_in[12];
    float* out = (float*)d_out;

    float *x1;
    cudaGetSymbolAddress((void**)&x1,  g_x1);

    __half *hhi, *chi, *ghi;
    __half *wqkvh, *woh, *w13h, *w2h;
    __half *qah, *kah, *vah;
    cudaGetSymbolAddress((void**)&hhi, t_h_hi);
    cudaGetSymbolAddress((void**)&chi, t_ctx_hi);
    cudaGetSymbolAddress((void**)&ghi, t_g_hi);
    cudaGetSymbolAddress((void**)&wqkvh, t_wqkv_hi);
    cudaGetSymbolAddress((void**)&woh, t_wo_hi);
    cudaGetSymbolAddress((void**)&w13h, t_w13_hi);
    cudaGetSymbolAddress((void**)&w2h, t_w2_hi);
    cudaGetSymbolAddress((void**)&qah, t_qat_hi);
    cudaGetSymbolAddress((void**)&kah, t_kat_hi);
    cudaGetSymbolAddress((void**)&vah, t_vat_hi);

    cudaFuncSetAttribute(mma_gemm, cudaFuncAttributeMaxDynamicSharedMemorySize, GEMM_SMEM);
    cudaFuncSetAttribute(attn_mma, cudaFuncAttributeMaxDynamicSharedMemorySize, ATT_SMEM);

    // weights -> tiled fp16
    conv_w<<<dim3(D_MODEL / 64, 16), 256>>>(wq, wqkvh, D_MODEL, D_MODEL, 0,  24);
    conv_w<<<dim3(D_MODEL / 64, 4),  256>>>(wk, wqkvh, D_MODEL, 512,     16, 24);
    conv_w<<<dim3(D_MODEL / 64, 4),  256>>>(wv, wqkvh, D_MODEL, 512,     20, 24);
    conv_w<<<dim3(D_MODEL / 64, 16), 256>>>(wo, woh,   D_MODEL, D_MODEL, 0,  16);
    conv_w13<<<dim3(D_MODEL / 64, 88), 256>>>(w1, w13h, 0);
    conv_w13<<<dim3(D_MODEL / 64, 88), 256>>>(w3, w13h, 64);
    conv_w<<<dim3(HID / 64,     16), 256>>>(w2, w2h,   HID,     D_MODEL, 0,  16);

    // h tiles = LN1(x)
    ln_tile<<<S_LEN, 256>>>(x, ln1w, ln1b, hhi);

    // qkv GEMM: rope Q/K -> attention tiles; V -> transposed tiles
    mma_gemm<<<dim3(QKV_N / 128, S_LEN / 128), 256, GEMM_SMEM>>>(hhi, wqkvh,
        nullptr, nullptr, S_LEN, QKV_N, D_MODEL, 1, qah, kah, vah);

    // attention -> ctx tiles
    attn_mma<<<dim3(S_LEN / 128, NH), 256, ATT_SMEM>>>(qah, kah, vah, mask, chi);

    // x1 = x + ctx @ wo (fp32)
    mma_gemm<<<dim3(D_MODEL / 128, S_LEN / 128), 256, GEMM_SMEM>>>(chi, woh,
        x, x1, S_LEN, D_MODEL, D_MODEL, 0, nullptr, nullptr, nullptr);

    // h tiles = LN2(x1)
    ln_tile<<<S_LEN, 256>>>(x1, ln2w, ln2b, hhi);

    // fused: gb tiles = silu(h @ w1) * (h @ w3)
    mma_gemm<<<dim3(W13_N / 128, S_LEN / 128), 256, GEMM_SMEM>>>(hhi, w13h,
        nullptr, nullptr, S_LEN, W13_N, D_MODEL, 3, ghi, nullptr, nullptr);

    // out = x1 + gb @ w2
    mma_gemm<<<dim3(D_MODEL / 128, S_LEN / 128), 256, GEMM_SMEM>>>(ghi, w2h,
        x1, out, S_LEN, D_MODEL, HID, 0, nullptr, nullptr, nullptr);
}